// round 8
// baseline (speedup 1.0000x reference)
#include <cuda_runtime.h>
#include <cuda_fp16.h>
#include <cstdint>
#include <math_constants.h>

#define BATCH 64
#define N 1024
#define RBLKS 32            // row-blocks per batch (32 rows each)

// Scratch: row offsets R[b][i], col offsets C[b][j], per-CTA column partials
__device__ float  g_R[BATCH * N];
__device__ float  g_C[BATCH * N];
__device__ __half g_parth[BATCH * RBLKS * N];   // 4 MB (half partials)

// ---------------------------------------------------------------------------
// Fused pass (one read of s does a row iteration AND a column iteration):
//   per row i:  sum_i = sum_j exp(s[i][j] - C[j]);  R[i] = log(sum_i)
//   column partials: part[j] += sum_i exp(s[i][j] - C[j] - R[i])
// finalize_col forms C_new[j] = log(sum_blocks part) + C_old[j].
//
// Software-pipelined: each warp owns 4 rows (row0 + 8g). After converting the
// current row's loads into (eh, sum), the NEXT row's 8x LDG.128 are issued
// BEFORE the serial tail (shfl reduce -> logf -> rcp -> HFMA2s), so the load
// stream never drains during tails. grid = (RBLKS, BATCH), block = 256.
// No max-subtraction needed: exp args bounded (logsumexp >= max).
// ---------------------------------------------------------------------------
template <bool USE_C>
__global__ void __launch_bounds__(256, 3) fused_pass(const float* __restrict__ s) {
    __shared__ float c_s[N];
    __shared__ float stage[8][N];      // 32 KB, used once at the end
    const int b = blockIdx.y;
    if (USE_C) {
        #pragma unroll
        for (int t = threadIdx.x; t < N; t += 256) c_s[t] = g_C[b * N + t];
        __syncthreads();
    }

    const int warp = threadIdx.x >> 5;
    const int lane = threadIdx.x & 31;
    const int tid  = threadIdx.x;
    const int row0 = (blockIdx.x << 5) + warp;
    const float* p = s + ((size_t)b << 20) + ((size_t)row0 << 10);

    __half2 cacc[16];
    #pragma unroll
    for (int k = 0; k < 16; k++) cacc[k] = __float2half2_rn(0.f);

    // prologue: loads for row g=0
    float4 sv[8];
    #pragma unroll
    for (int k = 0; k < 8; k++)
        sv[k] = __ldcs(reinterpret_cast<const float4*>(p + (lane << 2) + (k << 7)));

    #pragma unroll
    for (int g = 0; g < 4; g++) {
        // consume loads: exp + pack + per-thread sum (frees sv for prefetch)
        __half2 eh[16];
        float sum = 0.f;
        #pragma unroll
        for (int k = 0; k < 8; k++) {
            float4 v = sv[k];
            if (USE_C) {
                const float4 cv =
                    *reinterpret_cast<const float4*>(&c_s[(lane << 2) + (k << 7)]);
                v.x -= cv.x; v.y -= cv.y; v.z -= cv.z; v.w -= cv.w;
            }
            const float ex = __expf(v.x), ey = __expf(v.y);
            const float ez = __expf(v.z), ew = __expf(v.w);
            eh[2*k+0] = __floats2half2_rn(ex, ey);
            eh[2*k+1] = __floats2half2_rn(ez, ew);
            sum += (ex + ey) + (ez + ew);
        }

        // prefetch next row's loads BEFORE the serial tail
        if (g < 3) {
            const float* np = p + ((size_t)((g + 1) << 3) << 10);
            #pragma unroll
            for (int k = 0; k < 8; k++)
                sv[k] = __ldcs(reinterpret_cast<const float4*>(np + (lane << 2) + (k << 7)));
        }

        // serial tail (overlapped by the in-flight prefetch)
        #pragma unroll
        for (int off = 16; off; off >>= 1)
            sum += __shfl_xor_sync(0xffffffffu, sum, off);
        if (lane == 0) g_R[b * N + row0 + (g << 3)] = logf(sum);
        const __half2 rin = __float2half2_rn(__fdividef(1.f, sum));
        #pragma unroll
        for (int k = 0; k < 16; k++) cacc[k] = __hfma2(eh[k], rin, cacc[k]);
    }

    // single cross-warp reduce of column partials (fp32)
    #pragma unroll
    for (int k = 0; k < 8; k++) {
        const int j = (lane << 2) + (k << 7);
        const float2 lo = __half22float2(cacc[2*k+0]);
        const float2 hi = __half22float2(cacc[2*k+1]);
        *reinterpret_cast<float4*>(&stage[warp][j]) = make_float4(lo.x, lo.y, hi.x, hi.y);
    }
    __syncthreads();

    float4 a = make_float4(0.f, 0.f, 0.f, 0.f);
    #pragma unroll
    for (int w = 0; w < 8; w++) {
        float4 sv2 = *reinterpret_cast<const float4*>(&stage[w][tid << 2]);
        a.x += sv2.x; a.y += sv2.y; a.z += sv2.z; a.w += sv2.w;
    }
    // store partial as half (4 values -> 8 B, coalesced)
    const __half2 h0 = __floats2half2_rn(a.x, a.y);
    const __half2 h1 = __floats2half2_rn(a.z, a.w);
    const __half2_raw r0 = *reinterpret_cast<const __half2_raw*>(&h0);
    const __half2_raw r1 = *reinterpret_cast<const __half2_raw*>(&h1);
    uint2 u;
    u.x = ((unsigned int)r0.y << 16) | (unsigned int)r0.x;
    u.y = ((unsigned int)r1.y << 16) | (unsigned int)r1.x;
    reinterpret_cast<uint2*>(
        &g_parth[((size_t)(b * RBLKS + blockIdx.x)) * N])[tid] = u;
}

// ---------------------------------------------------------------------------
// Finalize: C_new[b][j] = log( sum over RBLKS half partials ) + C_old.
// FIRST=true: pass ran with C==0 -> write log(sum) directly (must NOT read
// g_C: it holds stale values from the previous graph replay).
// One thread per half2 (2 columns), MLP=32 coalesced. grid = 128 CTAs.
// ---------------------------------------------------------------------------
template <bool FIRST>
__global__ void __launch_bounds__(256) finalize_col() {
    const int q  = blockIdx.x * 256 + threadIdx.x;   // half2 index: b*512 + jh
    const int b  = q >> 9;
    const int jh = q & 511;
    float sx = 0.f, sy = 0.f;
    #pragma unroll
    for (int r = 0; r < RBLKS; r++) {
        const __half2 v = reinterpret_cast<const __half2*>(
            &g_parth[((size_t)(b * RBLKS + r)) * N])[jh];
        const float2 f = __half22float2(v);
        sx += f.x; sy += f.y;
    }
    float2* c2 = reinterpret_cast<float2*>(&g_C[b * N + (jh << 1)]);
    if (FIRST) {
        *c2 = make_float2(logf(sx), logf(sy));
    } else {
        const float2 c = *c2;
        *c2 = make_float2(logf(sx) + c.x, logf(sy) + c.y);
    }
}

// ---------------------------------------------------------------------------
// Output pass: out = exp(s - R[b][i] - C[b][j]), float4, streaming hints.
// ---------------------------------------------------------------------------
__global__ void __launch_bounds__(256) out_pass(const float4* __restrict__ s4,
                                                float4* __restrict__ o4) {
    const size_t gid  = (size_t)blockIdx.x * 256 + threadIdx.x;
    const size_t base = gid << 2;
    const int b = (int)(base >> 20);
    const int i = (int)(base >> 10) & (N - 1);
    const int j = (int)base & (N - 1);
    const float r = __ldg(&g_R[(b << 10) + i]);
    const float4 c = *reinterpret_cast<const float4*>(&g_C[(b << 10) + j]);
    float4 v = __ldcs(s4 + gid);
    float4 o;
    o.x = __expf(v.x - r - c.x);
    o.y = __expf(v.y - r - c.y);
    o.z = __expf(v.z - r - c.z);
    o.w = __expf(v.w - r - c.w);
    __stcs(o4 + gid, o);
}

// ---------------------------------------------------------------------------
extern "C" void kernel_launch(void* const* d_in, const int* in_sizes, int n_in,
                              void* d_out, int out_size) {
    const float* s = (const float*)d_in[0];
    float* out = (float*)d_out;

    const dim3 fgrid(RBLKS, BATCH);
    const int fin_blocks = BATCH * N / 2 / 256;       // 128
    const int out_blocks = (BATCH * N * N / 4) / 256;

    // iters 0+1
    fused_pass<false><<<fgrid, 256>>>(s);
    finalize_col<true><<<fin_blocks, 256>>>();
    // iters 2+3, 4+5, 6+7, 8+9
    fused_pass<true><<<fgrid, 256>>>(s);
    finalize_col<false><<<fin_blocks, 256>>>();
    fused_pass<true><<<fgrid, 256>>>(s);
    finalize_col<false><<<fin_blocks, 256>>>();
    fused_pass<true><<<fgrid, 256>>>(s);
    finalize_col<false><<<fin_blocks, 256>>>();
    fused_pass<true><<<fgrid, 256>>>(s);
    finalize_col<false><<<fin_blocks, 256>>>();

    out_pass<<<out_blocks, 256>>>((const float4*)s, (float4*)out);
}

// round 9
// speedup vs baseline: 1.0084x; 1.0084x over previous
#include <cuda_runtime.h>
#include <cuda_fp16.h>
#include <cstdint>
#include <math_constants.h>

#define BATCH 64
#define N 1024
#define RBLKS 32            // row-blocks per batch (32 rows each)

// Scratch (double-buffered across passes to avoid intra-pass races):
__device__ float  g_R[BATCH * N];
__device__ float  g_C[BATCH * N];                  // final C (for out_pass)
__device__ float  g_C2[2][BATCH * N];              // C accumulator ping-pong
__device__ __half g_parth[2][BATCH * RBLKS * N];   // 2 x 4 MB half partials

// ---------------------------------------------------------------------------
// Fused pass PASS (0..4). One read of s performs a row iteration AND a column
// iteration:
//   prologue (PASS>=1): C_new[j] = log(sum_r part_prev[r][j]) (+ C_old[j])
//     computed redundantly per-CTA from L2-resident partials into smem c_s;
//     CTA blockIdx.x==0 persists it to g_C2[WC] for the next pass.
//   per row i: sum_i = sum_j exp(s[i][j]-C[j]);  R[i] = log(sum_i)
//   column partials: part[j] += sum_i exp(s[i][j]-C[j]-R[i])  (half)
// Buffers: RP/WP partial read/write, RC/WC C read/write — alternate so no
// buffer is read and written in the same pass.
// Warp-per-row, 4 rows/warp. grid = (RBLKS, BATCH), block = 256.
// No max-subtraction needed: exp args bounded (logsumexp >= max).
// ---------------------------------------------------------------------------
template <int PASS>
__global__ void __launch_bounds__(256) fused_pass(const float* __restrict__ s) {
    constexpr bool USE_C = (PASS >= 1);
    constexpr int RP = 1 - (PASS & 1);   // partial buf written by previous pass
    constexpr int WP = (PASS & 1);
    constexpr int RC = (PASS & 1);       // C buf written by previous pass
    constexpr int WC = 1 - (PASS & 1);

    __shared__ float   c_s[N];           // 4 KB
    __shared__ __half2 stage[8][N / 2];  // 16 KB
    const int b   = blockIdx.y;
    const int tid = threadIdx.x;

    if (USE_C) {
        // ---- prologue: build C from previous pass's partials ----
        const __half* pb = g_parth[RP] + (size_t)b * (RBLKS * N);
        const int j4 = tid << 2;
        float s0 = 0.f, s1 = 0.f, s2 = 0.f, s3 = 0.f;
        #pragma unroll
        for (int r = 0; r < RBLKS; r++) {
            const uint2 u = *reinterpret_cast<const uint2*>(pb + (size_t)r * N + j4);
            const __half2 h0 = *reinterpret_cast<const __half2*>(&u.x);
            const __half2 h1 = *reinterpret_cast<const __half2*>(&u.y);
            const float2 f0 = __half22float2(h0), f1 = __half22float2(h1);
            s0 += f0.x; s1 += f0.y; s2 += f1.x; s3 += f1.y;
        }
        float4 c = make_float4(logf(s0), logf(s1), logf(s2), logf(s3));
        if (PASS >= 2) {
            const float4 co = *reinterpret_cast<const float4*>(&g_C2[RC][b * N + j4]);
            c.x += co.x; c.y += co.y; c.z += co.z; c.w += co.w;
        }
        *reinterpret_cast<float4*>(&c_s[j4]) = c;
        if (blockIdx.x == 0)
            *reinterpret_cast<float4*>(&g_C2[WC][b * N + j4]) = c;
        __syncthreads();
    }

    const int warp = tid >> 5;
    const int lane = tid & 31;

    __half2 cacc[16];
    #pragma unroll
    for (int k = 0; k < 16; k++) cacc[k] = __float2half2_rn(0.f);

    #pragma unroll 1
    for (int g = 0; g < 4; g++) {
        const int row = (blockIdx.x << 5) + (g << 3) + warp;
        const float* p = s + ((size_t)b << 20) + ((size_t)row << 10);

        __half2 eh[16];
        float sum = 0.f;
        #pragma unroll
        for (int k = 0; k < 8; k++) {
            const int j = (lane << 2) + (k << 7);
            float4 sv = __ldcs(reinterpret_cast<const float4*>(p + j));
            if (USE_C) {
                const float4 cv = *reinterpret_cast<const float4*>(&c_s[j]);
                sv.x -= cv.x; sv.y -= cv.y; sv.z -= cv.z; sv.w -= cv.w;
            }
            const float ex = __expf(sv.x), ey = __expf(sv.y);
            const float ez = __expf(sv.z), ew = __expf(sv.w);
            eh[2*k+0] = __floats2half2_rn(ex, ey);
            eh[2*k+1] = __floats2half2_rn(ez, ew);
            sum += (ex + ey) + (ez + ew);
        }
        #pragma unroll
        for (int off = 16; off; off >>= 1)
            sum += __shfl_xor_sync(0xffffffffu, sum, off);

        if (lane == 0) g_R[b * N + row] = logf(sum);  // final pass's R feeds out_pass
        const __half2 rin = __float2half2_rn(__fdividef(1.f, sum));
        #pragma unroll
        for (int k = 0; k < 16; k++) cacc[k] = __hfma2(eh[k], rin, cacc[k]);
    }

    // single cross-warp reduce of column partials (half2 staging, fp32 sum)
    #pragma unroll
    for (int k = 0; k < 8; k++) {
        const int jh = (lane << 1) + (k << 6);   // half2 index of col 4*lane+128*k
        stage[warp][jh]     = cacc[2*k+0];
        stage[warp][jh + 1] = cacc[2*k+1];
    }
    __syncthreads();

    float a0 = 0.f, a1 = 0.f, a2 = 0.f, a3 = 0.f;
    #pragma unroll
    for (int w = 0; w < 8; w++) {
        const float2 f0 = __half22float2(stage[w][(tid << 1)]);
        const float2 f1 = __half22float2(stage[w][(tid << 1) + 1]);
        a0 += f0.x; a1 += f0.y; a2 += f1.x; a3 += f1.y;
    }
    const __half2 h0 = __floats2half2_rn(a0, a1);
    const __half2 h1 = __floats2half2_rn(a2, a3);
    uint2 u;
    u.x = *reinterpret_cast<const unsigned int*>(&h0);
    u.y = *reinterpret_cast<const unsigned int*>(&h1);
    reinterpret_cast<uint2*>(
        g_parth[WP] + ((size_t)(b * RBLKS + blockIdx.x)) * N)[tid] = u;
}

// ---------------------------------------------------------------------------
// Final finalize (after PASS=4): C[b][j] = log(sum_r part[r][j]) + C_old.
// PASS=4 wrote partials to buf 0 and its own C to g_C2[1].
// ---------------------------------------------------------------------------
__global__ void __launch_bounds__(256) finalize_col() {
    const int q  = blockIdx.x * 256 + threadIdx.x;   // half2 index: b*512 + jh
    const int b  = q >> 9;
    const int jh = q & 511;
    float sx = 0.f, sy = 0.f;
    #pragma unroll
    for (int r = 0; r < RBLKS; r++) {
        const __half2 v = *reinterpret_cast<const __half2*>(
            g_parth[0] + ((size_t)(b * RBLKS + r)) * N + (jh << 1));
        const float2 f = __half22float2(v);
        sx += f.x; sy += f.y;
    }
    const float2 c = *reinterpret_cast<const float2*>(&g_C2[1][b * N + (jh << 1)]);
    *reinterpret_cast<float2*>(&g_C[b * N + (jh << 1)]) =
        make_float2(logf(sx) + c.x, logf(sy) + c.y);
}

// ---------------------------------------------------------------------------
// Output pass: out = exp(s - R[b][i] - C[b][j]), float4, streaming hints.
// ---------------------------------------------------------------------------
__global__ void __launch_bounds__(256) out_pass(const float4* __restrict__ s4,
                                                float4* __restrict__ o4) {
    const size_t gid  = (size_t)blockIdx.x * 256 + threadIdx.x;
    const size_t base = gid << 2;
    const int b = (int)(base >> 20);
    const int i = (int)(base >> 10) & (N - 1);
    const int j = (int)base & (N - 1);
    const float r = __ldg(&g_R[(b << 10) + i]);
    const float4 c = *reinterpret_cast<const float4*>(&g_C[(b << 10) + j]);
    float4 v = __ldcs(s4 + gid);
    float4 o;
    o.x = __expf(v.x - r - c.x);
    o.y = __expf(v.y - r - c.y);
    o.z = __expf(v.z - r - c.z);
    o.w = __expf(v.w - r - c.w);
    __stcs(o4 + gid, o);
}

// ---------------------------------------------------------------------------
extern "C" void kernel_launch(void* const* d_in, const int* in_sizes, int n_in,
                              void* d_out, int out_size) {
    const float* s = (const float*)d_in[0];
    float* out = (float*)d_out;

    const dim3 fgrid(RBLKS, BATCH);
    const int fin_blocks = BATCH * N / 2 / 256;       // 128
    const int out_blocks = (BATCH * N * N / 4) / 256;

    fused_pass<0><<<fgrid, 256>>>(s);   // iters 0+1
    fused_pass<1><<<fgrid, 256>>>(s);   // iters 2+3 (C from pass0 partials)
    fused_pass<2><<<fgrid, 256>>>(s);   // iters 4+5
    fused_pass<3><<<fgrid, 256>>>(s);   // iters 6+7
    fused_pass<4><<<fgrid, 256>>>(s);   // iters 8+9
    finalize_col<<<fin_blocks, 256>>>();
    out_pass<<<out_blocks, 256>>>((const float4*)s, (float4*)out);
}

// round 10
// speedup vs baseline: 1.1204x; 1.1111x over previous
#include <cuda_runtime.h>
#include <cuda_fp16.h>
#include <cstdint>
#include <math_constants.h>

#define BATCH 64
#define N 1024
#define RBLKS 32            // row-blocks per batch (32 rows each)

// Scratch: row offsets R, col offsets C, per-CTA column partials, exp cache
__device__ float  g_R[BATCH * N];
__device__ float  g_C[BATCH * N];
__device__ __half g_parth[BATCH * RBLKS * N];       // 4 MB half partials
__device__ __half g_e[(size_t)BATCH * N * N];       // 128 MB: exp(s) in fp16

// ---------------------------------------------------------------------------
// Pass 0 (iters 0+1): reads fp32 s ONCE, writes e = exp(s) as half for all
// later passes, computes R[i] = log(sum_j exp(s_ij)) and column partials
// part[j] += exp(s_ij - R_i). Warp-per-row, 4 rows/warp.
// grid = (RBLKS, BATCH), block = 256.
// ---------------------------------------------------------------------------
__global__ void __launch_bounds__(256) pass0(const float* __restrict__ s) {
    __shared__ __half2 stage[8][N / 2];   // 16 KB
    const int b    = blockIdx.y;
    const int tid  = threadIdx.x;
    const int warp = tid >> 5;
    const int lane = tid & 31;

    __half2 cacc[16];
    #pragma unroll
    for (int k = 0; k < 16; k++) cacc[k] = __float2half2_rn(0.f);

    #pragma unroll 1
    for (int g = 0; g < 4; g++) {
        const int row = (blockIdx.x << 5) + (g << 3) + warp;
        const float*  p  = s   + ((size_t)b << 20) + ((size_t)row << 10);
        __half*       ep = g_e + ((size_t)b << 20) + ((size_t)row << 10);

        __half2 eh[16];
        float sum = 0.f;
        #pragma unroll
        for (int k = 0; k < 8; k++) {
            const int j = (lane << 2) + (k << 7);
            const float4 sv = __ldcs(reinterpret_cast<const float4*>(p + j));
            const float ex = __expf(sv.x), ey = __expf(sv.y);
            const float ez = __expf(sv.z), ew = __expf(sv.w);
            const __half2 h0 = __floats2half2_rn(ex, ey);
            const __half2 h1 = __floats2half2_rn(ez, ew);
            eh[2*k+0] = h0; eh[2*k+1] = h1;
            uint2 u;
            u.x = *reinterpret_cast<const unsigned int*>(&h0);
            u.y = *reinterpret_cast<const unsigned int*>(&h1);
            __stcs(reinterpret_cast<uint2*>(ep + j), u);
            sum += (ex + ey) + (ez + ew);
        }
        #pragma unroll
        for (int off = 16; off; off >>= 1)
            sum += __shfl_xor_sync(0xffffffffu, sum, off);

        if (lane == 0) g_R[b * N + row] = logf(sum);
        const __half2 rin = __float2half2_rn(__fdividef(1.f, sum));
        #pragma unroll
        for (int k = 0; k < 16; k++) cacc[k] = __hfma2(eh[k], rin, cacc[k]);
    }

    // cross-warp reduce of column partials -> half partials
    #pragma unroll
    for (int k = 0; k < 8; k++) {
        const int jh = (lane << 1) + (k << 6);
        stage[warp][jh]     = cacc[2*k+0];
        stage[warp][jh + 1] = cacc[2*k+1];
    }
    __syncthreads();
    float a0 = 0.f, a1 = 0.f, a2 = 0.f, a3 = 0.f;
    #pragma unroll
    for (int w = 0; w < 8; w++) {
        const float2 f0 = __half22float2(stage[w][(tid << 1)]);
        const float2 f1 = __half22float2(stage[w][(tid << 1) + 1]);
        a0 += f0.x; a1 += f0.y; a2 += f1.x; a3 += f1.y;
    }
    const __half2 h0 = __floats2half2_rn(a0, a1);
    const __half2 h1 = __floats2half2_rn(a2, a3);
    uint2 u;
    u.x = *reinterpret_cast<const unsigned int*>(&h0);
    u.y = *reinterpret_cast<const unsigned int*>(&h1);
    reinterpret_cast<uint2*>(
        g_parth + ((size_t)(b * RBLKS + blockIdx.x)) * N)[tid] = u;
}

// ---------------------------------------------------------------------------
// Half passes (iter pairs 2+3 / 4+5 / 6+7 / 8+9): read ONLY the 128 MB half
// exp-cache. exp(s - C) = e * w with w[j] = exp(-C[j]) held fp32 in smem
// (fp32 w avoids systematic per-column rounding in the C update).
//   row:  sum_i = sum_j e_ij * w_j;  R[i] = log(sum_i)
//   cols: part[j] += e_ij * w_j / sum_i
// grid = (RBLKS, BATCH), block = 256, warp-per-row, 4 rows/warp.
// ---------------------------------------------------------------------------
__global__ void __launch_bounds__(256) pass_h() {
    __shared__ float   w_s[N];            // 4 KB
    __shared__ __half2 stage[8][N / 2];   // 16 KB
    const int b    = blockIdx.y;
    const int tid  = threadIdx.x;
    const int warp = tid >> 5;
    const int lane = tid & 31;

    // prologue: w = exp(-C)
    {
        const float4 c = *reinterpret_cast<const float4*>(&g_C[b * N + (tid << 2)]);
        const float4 w = make_float4(__expf(-c.x), __expf(-c.y),
                                     __expf(-c.z), __expf(-c.w));
        *reinterpret_cast<float4*>(&w_s[tid << 2]) = w;
    }
    __syncthreads();

    __half2 cacc[16];
    #pragma unroll
    for (int k = 0; k < 16; k++) cacc[k] = __float2half2_rn(0.f);

    #pragma unroll 1
    for (int g = 0; g < 4; g++) {
        const int row = (blockIdx.x << 5) + (g << 3) + warp;
        const __half* ep = g_e + ((size_t)b << 20) + ((size_t)row << 10);

        __half2 ph[16];
        float sum = 0.f;
        #pragma unroll
        for (int k = 0; k < 4; k++) {
            const int j = (lane << 3) + (k << 8);          // 8 elems per lane
            const uint4 u = __ldcs(reinterpret_cast<const uint4*>(ep + j));
            const float2 f0 = __half22float2(*reinterpret_cast<const __half2*>(&u.x));
            const float2 f1 = __half22float2(*reinterpret_cast<const __half2*>(&u.y));
            const float2 f2 = __half22float2(*reinterpret_cast<const __half2*>(&u.z));
            const float2 f3 = __half22float2(*reinterpret_cast<const __half2*>(&u.w));
            const float4 wa = *reinterpret_cast<const float4*>(&w_s[j]);
            const float4 wb = *reinterpret_cast<const float4*>(&w_s[j + 4]);
            const float p0 = f0.x * wa.x, p1 = f0.y * wa.y;
            const float p2 = f1.x * wa.z, p3 = f1.y * wa.w;
            const float p4 = f2.x * wb.x, p5 = f2.y * wb.y;
            const float p6 = f3.x * wb.z, p7 = f3.y * wb.w;
            sum += ((p0 + p1) + (p2 + p3)) + ((p4 + p5) + (p6 + p7));
            ph[4*k+0] = __floats2half2_rn(p0, p1);
            ph[4*k+1] = __floats2half2_rn(p2, p3);
            ph[4*k+2] = __floats2half2_rn(p4, p5);
            ph[4*k+3] = __floats2half2_rn(p6, p7);
        }
        #pragma unroll
        for (int off = 16; off; off >>= 1)
            sum += __shfl_xor_sync(0xffffffffu, sum, off);

        if (lane == 0) g_R[b * N + row] = logf(sum);   // last pass's R feeds out_pass
        const __half2 rin = __float2half2_rn(__fdividef(1.f, sum));
        #pragma unroll
        for (int k = 0; k < 16; k++) cacc[k] = __hfma2(ph[k], rin, cacc[k]);
    }

    // cross-warp reduce of column partials (cols: j = lane*8 + k*256 + m)
    #pragma unroll
    for (int k = 0; k < 4; k++) {
        const int jh = (lane << 2) + (k << 7);
        #pragma unroll
        for (int m = 0; m < 4; m++) stage[warp][jh + m] = cacc[4*k + m];
    }
    __syncthreads();
    float a0 = 0.f, a1 = 0.f, a2 = 0.f, a3 = 0.f;
    #pragma unroll
    for (int w = 0; w < 8; w++) {
        const float2 f0 = __half22float2(stage[w][(tid << 1)]);
        const float2 f1 = __half22float2(stage[w][(tid << 1) + 1]);
        a0 += f0.x; a1 += f0.y; a2 += f1.x; a3 += f1.y;
    }
    const __half2 h0 = __floats2half2_rn(a0, a1);
    const __half2 h1 = __floats2half2_rn(a2, a3);
    uint2 u;
    u.x = *reinterpret_cast<const unsigned int*>(&h0);
    u.y = *reinterpret_cast<const unsigned int*>(&h1);
    reinterpret_cast<uint2*>(
        g_parth + ((size_t)(b * RBLKS + blockIdx.x)) * N)[tid] = u;
}

// ---------------------------------------------------------------------------
// Finalize: C_new[b][j] = log( sum over RBLKS half partials ) + C_old.
// FIRST=true: the pass ran with C==0 -> write log(sum) directly (must NOT
// read g_C: stale from the previous graph replay). grid = 128 CTAs.
// ---------------------------------------------------------------------------
template <bool FIRST>
__global__ void __launch_bounds__(256) finalize_col() {
    const int q  = blockIdx.x * 256 + threadIdx.x;   // half2 index: b*512 + jh
    const int b  = q >> 9;
    const int jh = q & 511;
    float sx = 0.f, sy = 0.f;
    #pragma unroll
    for (int r = 0; r < RBLKS; r++) {
        const __half2 v = *reinterpret_cast<const __half2*>(
            g_parth + ((size_t)(b * RBLKS + r)) * N + (jh << 1));
        const float2 f = __half22float2(v);
        sx += f.x; sy += f.y;
    }
    float2* c2 = reinterpret_cast<float2*>(&g_C[b * N + (jh << 1)]);
    if (FIRST) {
        *c2 = make_float2(logf(sx), logf(sy));
    } else {
        const float2 c = *c2;
        *c2 = make_float2(logf(sx) + c.x, logf(sy) + c.y);
    }
}

// ---------------------------------------------------------------------------
// Output pass: out = exp(s - R[b][i] - C[b][j]), fp32 s, float4, streaming.
// ---------------------------------------------------------------------------
__global__ void __launch_bounds__(256) out_pass(const float4* __restrict__ s4,
                                                float4* __restrict__ o4) {
    const size_t gid  = (size_t)blockIdx.x * 256 + threadIdx.x;
    const size_t base = gid << 2;
    const int b = (int)(base >> 20);
    const int i = (int)(base >> 10) & (N - 1);
    const int j = (int)base & (N - 1);
    const float r = __ldg(&g_R[(b << 10) + i]);
    const float4 c = *reinterpret_cast<const float4*>(&g_C[(b << 10) + j]);
    float4 v = __ldcs(s4 + gid);
    float4 o;
    o.x = __expf(v.x - r - c.x);
    o.y = __expf(v.y - r - c.y);
    o.z = __expf(v.z - r - c.z);
    o.w = __expf(v.w - r - c.w);
    __stcs(o4 + gid, o);
}

// ---------------------------------------------------------------------------
extern "C" void kernel_launch(void* const* d_in, const int* in_sizes, int n_in,
                              void* d_out, int out_size) {
    const float* s = (const float*)d_in[0];
    float* out = (float*)d_out;

    const dim3 fgrid(RBLKS, BATCH);
    const int fin_blocks = BATCH * N / 2 / 256;       // 128
    const int out_blocks = (BATCH * N * N / 4) / 256;

    pass0<<<fgrid, 256>>>(s);                 // iters 0+1, builds exp cache
    finalize_col<true><<<fin_blocks, 256>>>();
    pass_h<<<fgrid, 256>>>();                 // iters 2+3
    finalize_col<false><<<fin_blocks, 256>>>();
    pass_h<<<fgrid, 256>>>();                 // iters 4+5
    finalize_col<false><<<fin_blocks, 256>>>();
    pass_h<<<fgrid, 256>>>();                 // iters 6+7
    finalize_col<false><<<fin_blocks, 256>>>();
    pass_h<<<fgrid, 256>>>();                 // iters 8+9
    finalize_col<false><<<fin_blocks, 256>>>();

    out_pass<<<out_blocks, 256>>>((const float4*)s, (float4*)out);
}